// round 5
// baseline (speedup 1.0000x reference)
#include <cuda_runtime.h>

#define N_SUBDOCS 4096
#define N_WORDS   128
#define DIM       768
#define N_DOCS    256

// scratch for per-subdoc pooled logits (allocation-free per harness rules)
__device__ float g_zpool[N_SUBDOCS];

// Kernel 1: per-subdoc word softmax-pool. (exact R1 structure — measured 225us)
// One CTA per subdoc, 512 threads (16 warps). Each warp handles 8 words.
// W kept in registers (same lane-strided layout as the embedding loads).
__global__ __launch_bounds__(512) void pool_words_kernel(
    const float* __restrict__ emb,   // [N_SUBDOCS, N_WORDS, DIM]
    const float* __restrict__ W,     // [DIM]
    const float* __restrict__ b,     // [1]
    const float* __restrict__ logt,  // [1]
    float* __restrict__ zpool)       // [N_SUBDOCS]
{
    __shared__ float sz[N_WORDS];

    const int tid  = threadIdx.x;
    const int lane = tid & 31;
    const int warp = tid >> 5;

    // Load W into registers: lane i holds W4[i], W4[i+32], ..., W4[i+160]
    float4 wreg[6];
    const float4* W4 = reinterpret_cast<const float4*>(W);
    #pragma unroll
    for (int i = 0; i < 6; i++) wreg[i] = W4[lane + i * 32];
    const float bias = b[0];

    const float* base = emb + (size_t)blockIdx.x * (N_WORDS * DIM);

    #pragma unroll
    for (int w = warp; w < N_WORDS; w += 16) {
        const float4* row = reinterpret_cast<const float4*>(base + w * DIM);
        float acc = 0.f;
        #pragma unroll
        for (int i = 0; i < 6; i++) {
            float4 e = row[lane + i * 32];
            acc += e.x * wreg[i].x + e.y * wreg[i].y
                 + e.z * wreg[i].z + e.w * wreg[i].w;
        }
        #pragma unroll
        for (int o = 16; o; o >>= 1) acc += __shfl_xor_sync(0xffffffffu, acc, o);
        if (lane == 0) sz[w] = acc + bias;
    }
    __syncthreads();

    // Warp 0: softmax-pool over the 128 word logits: sum(z * softmax(t*z))
    if (warp == 0) {
        const float t = expf(logt[0]);
        float v[4];
        float m = -1e30f;
        #pragma unroll
        for (int i = 0; i < 4; i++) {
            v[i] = sz[lane + 32 * i];
            m = fmaxf(m, t * v[i]);
        }
        #pragma unroll
        for (int o = 16; o; o >>= 1)
            m = fmaxf(m, __shfl_xor_sync(0xffffffffu, m, o));
        float se = 0.f, sn = 0.f;
        #pragma unroll
        for (int i = 0; i < 4; i++) {
            float e = expf(t * v[i] - m);
            se += e;
            sn += v[i] * e;
        }
        #pragma unroll
        for (int o = 16; o; o >>= 1) {
            se += __shfl_xor_sync(0xffffffffu, se, o);
            sn += __shfl_xor_sync(0xffffffffu, sn, o);
        }
        if (lane == 0) zpool[blockIdx.x] = sn / se;
    }
}

// Kernel 2: ragged segment softmax-pool + sigmoid. One WARP per doc,
// zero __syncthreads. Start offset = masked sum of lens[0..doc-1]
// (8 strided loads per lane + shuffle reduce; lens is L2-broadcast).
__global__ __launch_bounds__(32) void pool_docs_kernel(
    const float* __restrict__ zpool,  // [N_SUBDOCS]
    const int* __restrict__ lens,     // [N_DOCS]
    const float* __restrict__ logt,   // [1]
    float* __restrict__ out)          // [N_DOCS]
{
    const int doc  = blockIdx.x;
    const int lane = threadIdx.x;

    // start = sum of lens[j] for j < doc ; also grab this doc's length
    int part = 0;
    #pragma unroll
    for (int i = 0; i < N_DOCS / 32; i++) {
        int j = lane + i * 32;
        int l = lens[j];
        if (j < doc) part += l;
    }
    #pragma unroll
    for (int o = 16; o; o >>= 1)
        part += __shfl_xor_sync(0xffffffffu, part, o);
    const int start = part;
    const int len   = lens[doc];
    const float t   = expf(logt[0]);

    // pool this doc's segment (len <= 32 assumed per lane coverage; loop
    // handles longer segments too)
    float m = -1e30f;
    for (int i = lane; i < len; i += 32)
        m = fmaxf(m, t * zpool[start + i]);
    #pragma unroll
    for (int o = 16; o; o >>= 1)
        m = fmaxf(m, __shfl_xor_sync(0xffffffffu, m, o));

    float se = 0.f, sn = 0.f;
    for (int i = lane; i < len; i += 32) {
        float z = zpool[start + i];
        float e = expf(t * z - m);
        se += e;
        sn += z * e;
    }
    #pragma unroll
    for (int o = 16; o; o >>= 1) {
        se += __shfl_xor_sync(0xffffffffu, se, o);
        sn += __shfl_xor_sync(0xffffffffu, sn, o);
    }

    if (lane == 0) {
        float zp = sn / se;
        out[doc] = 1.f / (1.f + expf(-zp));
    }
}

extern "C" void kernel_launch(void* const* d_in, const int* in_sizes, int n_in,
                              void* d_out, int out_size) {
    const float* emb  = (const float*)d_in[0];  // embeddings [4096,128,768] f32
    const float* W    = (const float*)d_in[1];  // [1,768] f32
    const float* b    = (const float*)d_in[2];  // [1] f32
    const float* logt = (const float*)d_in[3];  // [1] f32
    const int*   lens = (const int*)d_in[4];    // [256] i32
    float* out = (float*)d_out;                 // [256] f32

    float* zpool = nullptr;
    cudaGetSymbolAddress((void**)&zpool, g_zpool);

    pool_words_kernel<<<N_SUBDOCS, 512>>>(emb, W, b, logt, zpool);
    pool_docs_kernel<<<N_DOCS, 32>>>(zpool, lens, logt, out);
}